// round 4
// baseline (speedup 1.0000x reference)
#include <cuda_runtime.h>

// CRF Viterbi decode: B=1024, T=512, C=48
// inputs: 0=potentials (B,T,C) f32, 1=sequence_lengths (B,1) i32, 2=transitions (C,C) f32
// output: one_hot(tags, C) f32 (B,T,C)

#define BB 1024
#define TT 512
#define CC 48

__global__ __launch_bounds__(CC, 8)
void viterbi_kernel(const float* __restrict__ pot,
                    const int*   __restrict__ seq_len,
                    const float* __restrict__ trans,
                    float*       __restrict__ out)
{
    __shared__ float         s_score[2][CC];
    __shared__ unsigned char s_bp[(TT - 1) * CC];   // bp[t-1][j], t = 1..L-1
    __shared__ unsigned char s_tags[TT];

    const int b = blockIdx.x;
    const int j = threadIdx.x;   // class index owned by this thread

    // transitions column j -> registers (coalesced across lanes for each i)
    float c[CC];
#pragma unroll
    for (int i = 0; i < CC; ++i) c[i] = trans[i * CC + j];

    const float* potb = pot + (size_t)b * TT * CC;
    int L = seq_len[b];
    if (L > TT) L = TT;
    if (L < 1)  L = 1;

    // init score = potentials[b, 0]
    s_score[0][j] = potb[j];
    __syncthreads();

    int buf = 0;
    for (int t = 1; t < L; ++t) {
        // prefetch potential for this step early (consumed after inner loop)
        float pv = potb[t * CC + j];

        // pull score vector into registers via vectorized shared loads
        float sc[CC];
        const float4* s4 = reinterpret_cast<const float4*>(s_score[buf]);
#pragma unroll
        for (int q = 0; q < CC / 4; ++q) {
            float4 v = s4[q];
            sc[4 * q + 0] = v.x; sc[4 * q + 1] = v.y;
            sc[4 * q + 2] = v.z; sc[4 * q + 3] = v.w;
        }

        // new_score[j] = max_i(score[i] + trans[i][j]); first-max wins (strict >)
        float best = sc[0] + c[0];
        int   arg  = 0;
#pragma unroll
        for (int i = 1; i < CC; ++i) {
            float v = sc[i] + c[i];
            if (v > best) { best = v; arg = i; }
        }

        s_bp[(t - 1) * CC + j] = (unsigned char)arg;
        s_score[buf ^ 1][j] = best + pv;
        buf ^= 1;
        __syncthreads();   // one barrier/step: separates this step's reads of old buf
                           // from next step's writes to it (ping-pong)
    }

    // serial final argmax + backtrack (thread 0); chain is shared-mem only
    if (j == 0) {
        float bestv = s_score[buf][0];
        int tag = 0;
#pragma unroll
        for (int i = 1; i < CC; ++i) {
            float v = s_score[buf][i];
            if (v > bestv) { bestv = v; tag = i; }
        }
        // t >= L-1: bp is identity in reference -> tag constant
        for (int t = TT - 1; t >= L - 1; --t) s_tags[t] = (unsigned char)tag;
        // real backtrack through stored bps
        for (int t = L - 1; t >= 1; --t) {
            tag = s_bp[(t - 1) * CC + tag];
            s_tags[t - 1] = (unsigned char)tag;
        }
    }
    __syncthreads();

    // one-hot output: 192 B per row, written as float4 (12 quads/row), coalesced
    float4* ob = reinterpret_cast<float4*>(out + (size_t)b * TT * CC);
    const int NQ = TT * (CC / 4);   // 6144 float4 per batch row
    for (int q = j; q < NQ; q += CC) {
        int t   = q / (CC / 4);
        int r   = q % (CC / 4);
        int tag = s_tags[t];
        int e   = r * 4;
        float4 v;
        v.x = (e + 0 == tag) ? 1.0f : 0.0f;
        v.y = (e + 1 == tag) ? 1.0f : 0.0f;
        v.z = (e + 2 == tag) ? 1.0f : 0.0f;
        v.w = (e + 3 == tag) ? 1.0f : 0.0f;
        ob[q] = v;
    }
}

extern "C" void kernel_launch(void* const* d_in, const int* in_sizes, int n_in,
                              void* d_out, int out_size)
{
    const float* pot     = (const float*)d_in[0];
    const int*   seqlen  = (const int*)d_in[1];
    const float* trans   = (const float*)d_in[2];
    float*       out     = (float*)d_out;

    viterbi_kernel<<<BB, CC>>>(pot, seqlen, trans, out);
}

// round 5
// speedup vs baseline: 1.0547x; 1.0547x over previous
#include <cuda_runtime.h>

// CRF Viterbi decode: B=1024, T=512, C=48
// inputs: 0=potentials (B,T,C) f32, 1=sequence_lengths (B,1) i32, 2=transitions (C,C) f32
// output: one_hot(tags, C) f32 (B,T,C)

#define BB 1024
#define TT 512
#define CC 48

__global__ __launch_bounds__(CC, 8)
void viterbi_kernel(const float* __restrict__ pot,
                    const int*   __restrict__ seq_len,
                    const float* __restrict__ trans,
                    float*       __restrict__ out)
{
    __shared__ float         s_score[2][CC];
    __shared__ unsigned char s_bp[(TT - 1) * CC];   // bp[t-1][j], t = 1..L-1
    __shared__ unsigned char s_tags[TT];
    __shared__ int           s_lasttag;

    const int b = blockIdx.x;
    const int j = threadIdx.x;   // class index owned by this thread

    // transitions column j -> registers (coalesced across lanes for each i)
    float c[CC];
#pragma unroll
    for (int i = 0; i < CC; ++i) c[i] = trans[i * CC + j];

    const float* potb = pot + (size_t)b * TT * CC;
    int L = seq_len[b];
    if (L > TT) L = TT;
    if (L < 1)  L = 1;

    // init score = potentials[b, 0]
    s_score[0][j] = potb[j];
    __syncthreads();

    int buf = 0;
    for (int t = 1; t < L; ++t) {
        // prefetch potential for this step early (consumed at the end)
        float pv = potb[t * CC + j];

        // pull score vector into registers via vectorized shared loads
        float sc[CC];
        const float4* s4 = reinterpret_cast<const float4*>(s_score[buf]);
#pragma unroll
        for (int q = 0; q < CC / 4; ++q) {
            float4 v = s4[q];
            sc[4 * q + 0] = v.x; sc[4 * q + 1] = v.y;
            sc[4 * q + 2] = v.z; sc[4 * q + 3] = v.w;
        }

        // argmax_i(sc[i] + c[i]) with first-max tie-break, via pairwise tree.
        // Node rule: take RIGHT child only on strict '>' (left subtree always
        // holds lower indices) => reproduces jnp.argmax first-occurrence.
        float val[24]; int id[24];

        // level 0 (fused with the add): 48 -> 24
#pragma unroll
        for (int q = 0; q < 24; ++q) {
            float a  = sc[2 * q]     + c[2 * q];
            float bb = sc[2 * q + 1] + c[2 * q + 1];
            bool  p  = bb > a;
            val[q] = p ? bb : a;
            id[q]  = p ? (2 * q + 1) : (2 * q);
        }
        // 24 -> 12
#pragma unroll
        for (int q = 0; q < 12; ++q) {
            bool p = val[2 * q + 1] > val[2 * q];
            val[q] = p ? val[2 * q + 1] : val[2 * q];
            id[q]  = p ? id[2 * q + 1]  : id[2 * q];
        }
        // 12 -> 6
#pragma unroll
        for (int q = 0; q < 6; ++q) {
            bool p = val[2 * q + 1] > val[2 * q];
            val[q] = p ? val[2 * q + 1] : val[2 * q];
            id[q]  = p ? id[2 * q + 1]  : id[2 * q];
        }
        // 6 -> 3
#pragma unroll
        for (int q = 0; q < 3; ++q) {
            bool p = val[2 * q + 1] > val[2 * q];
            val[q] = p ? val[2 * q + 1] : val[2 * q];
            id[q]  = p ? id[2 * q + 1]  : id[2 * q];
        }
        // 3 -> 1 (left-to-right keeps lower-index preference)
        bool p1 = val[1] > val[0];
        float bv = p1 ? val[1] : val[0];
        int   bi = p1 ? id[1]  : id[0];
        bool p2 = val[2] > bv;
        bv = p2 ? val[2] : bv;
        bi = p2 ? id[2]  : bi;

        s_bp[(t - 1) * CC + j] = (unsigned char)bi;
        s_score[buf ^ 1][j] = bv + pv;
        buf ^= 1;
        __syncthreads();   // ping-pong: one barrier per step
    }

    // final argmax over last score (runs once per block; serial is fine)
    if (j == 0) {
        float bestv = s_score[buf][0];
        int tag = 0;
#pragma unroll
        for (int i = 1; i < CC; ++i) {
            float v = s_score[buf][i];
            if (v > bestv) { bestv = v; tag = i; }
        }
        s_lasttag = tag;
    }
    __syncthreads();

    const int tag0 = s_lasttag;
    // parallel fill of the identity tail: t in [L-1, TT-1] gets the final tag
    for (int t = L - 1 + j; t < TT; t += CC) s_tags[t] = (unsigned char)tag0;

    // serial backtrack through stored bps (thread 0; shared-mem pointer chase)
    if (j == 0) {
        int tag = tag0;
        for (int t = L - 1; t >= 1; --t) {
            tag = s_bp[(t - 1) * CC + tag];
            s_tags[t - 1] = (unsigned char)tag;
        }
    }
    __syncthreads();

    // one-hot output: 192 B per row, written as float4 (12 quads/row), coalesced
    float4* ob = reinterpret_cast<float4*>(out + (size_t)b * TT * CC);
    const int NQ = TT * (CC / 4);   // 6144 float4 per batch row
    for (int q = j; q < NQ; q += CC) {
        int t   = q / (CC / 4);
        int r   = q % (CC / 4);
        int tag = s_tags[t];
        int e   = r * 4;
        float4 v;
        v.x = (e + 0 == tag) ? 1.0f : 0.0f;
        v.y = (e + 1 == tag) ? 1.0f : 0.0f;
        v.z = (e + 2 == tag) ? 1.0f : 0.0f;
        v.w = (e + 3 == tag) ? 1.0f : 0.0f;
        ob[q] = v;
    }
}

extern "C" void kernel_launch(void* const* d_in, const int* in_sizes, int n_in,
                              void* d_out, int out_size)
{
    const float* pot     = (const float*)d_in[0];
    const int*   seqlen  = (const int*)d_in[1];
    const float* trans   = (const float*)d_in[2];
    float*       out     = (float*)d_out;

    viterbi_kernel<<<BB, CC>>>(pot, seqlen, trans, out);
}

// round 8
// speedup vs baseline: 1.4113x; 1.3381x over previous
#include <cuda_runtime.h>

// CRF Viterbi decode: B=1024, T=512, C=48
// inputs: 0=potentials (B,T,C) f32, 1=sequence_lengths (B,1) i32, 2=transitions (C,C) f32
// output: one_hot(tags, C) f32 (B,T,C)
//
// Layout: 96 threads/block; thread pair (2j, 2j+1) owns class j.
// Even lane reduces source classes i in [0,24), odd lane i in [24,48);
// combined via shfl_xor(1) with exact first-max tie-break.

#define BB   1024
#define TT   512
#define CC   48
#define HALF 24
#define NTH  (2 * CC)   // 96

// two independent round-to-nearest fp32 adds in one instruction (bitwise == FADD.RN)
__device__ __forceinline__ void addf32x2(float &o0, float &o1,
                                         float a0, float a1,
                                         float b0, float b1)
{
    asm("{\n\t"
        ".reg .b64 ra, rb, rc;\n\t"
        "mov.b64 ra, {%2,%3};\n\t"
        "mov.b64 rb, {%4,%5};\n\t"
        "add.rn.f32x2 rc, ra, rb;\n\t"
        "mov.b64 {%0,%1}, rc;\n\t"
        "}"
        : "=f"(o0), "=f"(o1)
        : "f"(a0), "f"(a1), "f"(b0), "f"(b1));
}

__global__ __launch_bounds__(NTH, 8)
void viterbi_kernel(const float* __restrict__ pot,
                    const int*   __restrict__ seq_len,
                    const float* __restrict__ trans,
                    float*       __restrict__ out)
{
    __shared__ float         s_score[2][CC];
    __shared__ unsigned char s_bp[(TT - 1) * CC];   // bp[t-1][j]
    __shared__ unsigned char s_tags[TT];
    __shared__ int           s_lasttag;

    const int b   = blockIdx.x;
    const int tid = threadIdx.x;
    const int j   = tid >> 1;    // class owned by this pair
    const int h   = tid & 1;     // which half of the sources

    // this thread's 24 transition values: trans[h*24+k][j]
    float c[HALF];
#pragma unroll
    for (int k = 0; k < HALF; ++k)
        c[k] = trans[(h * HALF + k) * CC + j];

    const float* potb = pot + (size_t)b * TT * CC;
    int L = seq_len[b];
    if (L > TT) L = TT;
    if (L < 1)  L = 1;

    if (h == 0) s_score[0][j] = potb[j];
    __syncthreads();

    int buf = 0;
    for (int t = 1; t < L; ++t) {
        float pv = potb[t * CC + j];

        // this thread's 24 scores (96-byte-aligned float4 loads)
        float sc[HALF];
        const float4* s4 = reinterpret_cast<const float4*>(&s_score[buf][h * HALF]);
#pragma unroll
        for (int q = 0; q < HALF / 4; ++q) {
            float4 v4 = s4[q];
            sc[4 * q + 0] = v4.x; sc[4 * q + 1] = v4.y;
            sc[4 * q + 2] = v4.z; sc[4 * q + 3] = v4.w;
        }

        // sums via packed f32x2 adds (12 instructions)
        float v[HALF];
#pragma unroll
        for (int q = 0; q < HALF / 2; ++q)
            addf32x2(v[2 * q], v[2 * q + 1],
                     sc[2 * q], sc[2 * q + 1],
                     c[2 * q],  c[2 * q + 1]);

        // local argmax tree 24->12->6->3->1; strict '>' takes the
        // higher-index side only => first-max-wins
        float val[12]; int id[12];
#pragma unroll
        for (int q = 0; q < 12; ++q) {
            bool p = v[2 * q + 1] > v[2 * q];
            val[q] = p ? v[2 * q + 1] : v[2 * q];
            id[q]  = p ? (2 * q + 1) : (2 * q);
        }
#pragma unroll
        for (int q = 0; q < 6; ++q) {
            bool p = val[2 * q + 1] > val[2 * q];
            val[q] = p ? val[2 * q + 1] : val[2 * q];
            id[q]  = p ? id[2 * q + 1]  : id[2 * q];
        }
#pragma unroll
        for (int q = 0; q < 3; ++q) {
            bool p = val[2 * q + 1] > val[2 * q];
            val[q] = p ? val[2 * q + 1] : val[2 * q];
            id[q]  = p ? id[2 * q + 1]  : id[2 * q];
        }
        bool  p1 = val[1] > val[0];
        float mv = p1 ? val[1] : val[0];
        int   ma = p1 ? id[1]  : id[0];
        bool  p2 = val[2] > mv;
        mv = p2 ? val[2] : mv;
        ma = p2 ? id[2]  : ma;
        ma += h * HALF;                 // globalize the index

        // combine the two halves (same warp: pair lanes 2j,2j+1)
        float ov = __shfl_xor_sync(0xFFFFFFFFu, mv, 1);
        int   oa = __shfl_xor_sync(0xFFFFFFFFu, ma, 1);

        // lo = lower-index half, hi = upper; take hi only on strict '>'
        float lo_v = h ? ov : mv;  int lo_a = h ? oa : ma;
        float hi_v = h ? mv : ov;  int hi_a = h ? ma : oa;
        bool  p  = hi_v > lo_v;
        float bv = p ? hi_v : lo_v;
        int   bi = p ? hi_a : lo_a;

        // split the stores between the pair
        if (h) s_score[buf ^ 1][j]   = bv + pv;
        else   s_bp[(t - 1) * CC + j] = (unsigned char)bi;
        buf ^= 1;
        __syncthreads();   // ping-pong: one barrier per step
    }

    // final argmax over last score (first-max wins)
    if (tid == 0) {
        float bestv = s_score[buf][0];
        int tag = 0;
#pragma unroll
        for (int i = 1; i < CC; ++i) {
            float v = s_score[buf][i];
            if (v > bestv) { bestv = v; tag = i; }
        }
        s_lasttag = tag;
    }
    __syncthreads();

    const int tag0 = s_lasttag;
    // parallel fill of the identity tail
    for (int t = L - 1 + tid; t < TT; t += NTH) s_tags[t] = (unsigned char)tag0;

    // serial backtrack (shared-mem pointer chase, thread 0)
    if (tid == 0) {
        int tag = tag0;
        for (int t = L - 1; t >= 1; --t) {
            tag = s_bp[(t - 1) * CC + tag];
            s_tags[t - 1] = (unsigned char)tag;
        }
    }
    __syncthreads();

    // one-hot output: float4 stores, coalesced
    float4* ob = reinterpret_cast<float4*>(out + (size_t)b * TT * CC);
    const int NQ = TT * (CC / 4);   // 6144 quads per batch row
    for (int q = tid; q < NQ; q += NTH) {
        int t   = q / (CC / 4);
        int r   = q % (CC / 4);
        int tag = s_tags[t];
        int e   = r * 4;
        float4 v;
        v.x = (e + 0 == tag) ? 1.0f : 0.0f;
        v.y = (e + 1 == tag) ? 1.0f : 0.0f;
        v.z = (e + 2 == tag) ? 1.0f : 0.0f;
        v.w = (e + 3 == tag) ? 1.0f : 0.0f;
        ob[q] = v;
    }
}

extern "C" void kernel_launch(void* const* d_in, const int* in_sizes, int n_in,
                              void* d_out, int out_size)
{
    const float* pot    = (const float*)d_in[0];
    const int*   seqlen = (const int*)d_in[1];
    const float* trans  = (const float*)d_in[2];
    float*       out    = (float*)d_out;

    viterbi_kernel<<<BB, NTH>>>(pot, seqlen, trans, out);
}

// round 9
// speedup vs baseline: 1.4410x; 1.0211x over previous
#include <cuda_runtime.h>

// CRF Viterbi decode: B=1024, T=512, C=48
// inputs: 0=potentials (B,T,C) f32, 1=sequence_lengths (B,1) i32, 2=transitions (C,C) f32
// output: one_hot(tags, C) f32 (B,T,C)
//
// R9: persistent blocks + dynamic longest-first batch scheduling.
//  - order_kernel: counting-sort batch ids by descending L, reset work counter.
//  - viterbi_kernel: 592 persistent blocks, 96 threads; pair (2j,2j+1) owns class j.

#define BB   1024
#define TT   512
#define CC   48
#define HALF 24
#define NTH  (2 * CC)      // 96
#define NBLK 592           // 4 blocks per SM on 148-SM GB300

__device__ int g_order[BB];
__device__ int g_counter;

// two independent round-to-nearest fp32 adds in one instruction (bitwise == FADD.RN)
__device__ __forceinline__ void addf32x2(float &o0, float &o1,
                                         float a0, float a1,
                                         float b0, float b1)
{
    asm("{\n\t"
        ".reg .b64 ra, rb, rc;\n\t"
        "mov.b64 ra, {%2,%3};\n\t"
        "mov.b64 rb, {%4,%5};\n\t"
        "add.rn.f32x2 rc, ra, rb;\n\t"
        "mov.b64 {%0,%1}, rc;\n\t"
        "}"
        : "=f"(o0), "=f"(o1)
        : "f"(a0), "f"(a1), "f"(b0), "f"(b1));
}

// Counting sort of batch ids by descending sequence length; resets counter.
__global__ void order_kernel(const int* __restrict__ seq_len)
{
    __shared__ int hist[TT];
    __shared__ int offs[TT];
    const int tid = threadIdx.x;        // 512 threads

    hist[tid] = 0;
    __syncthreads();

    for (int b = tid; b < BB; b += TT) {
        int L = seq_len[b];
        if (L < 0) L = 0;
        if (L > TT - 1) L = TT - 1;
        atomicAdd(&hist[L], 1);
    }
    __syncthreads();

    if (tid == 0) {
        int acc = 0;
        for (int L = TT - 1; L >= 0; --L) { offs[L] = acc; acc += hist[L]; }
        g_counter = 0;
    }
    __syncthreads();

    for (int b = tid; b < BB; b += TT) {
        int L = seq_len[b];
        if (L < 0) L = 0;
        if (L > TT - 1) L = TT - 1;
        int pos = atomicAdd(&offs[L], 1);
        g_order[pos] = b;
    }
}

__global__ __launch_bounds__(NTH, 8)
void viterbi_kernel(const float* __restrict__ pot,
                    const int*   __restrict__ seq_len,
                    const float* __restrict__ trans,
                    float*       __restrict__ out)
{
    __shared__ float         s_score[2][CC];
    __shared__ unsigned char s_bp[(TT - 1) * CC];   // bp[t-1][j]
    __shared__ unsigned char s_tags[TT];
    __shared__ int           s_lasttag;
    __shared__ int           s_batch;

    const int tid = threadIdx.x;
    const int j   = tid >> 1;    // class owned by this pair
    const int h   = tid & 1;     // which half of the sources

    // this thread's 24 transition values: trans[h*24+k][j] (loop-invariant)
    float c[HALF];
#pragma unroll
    for (int k = 0; k < HALF; ++k)
        c[k] = trans[(h * HALF + k) * CC + j];

    for (;;) {
        __syncthreads();                       // protect s_batch / smem reuse
        if (tid == 0) s_batch = atomicAdd(&g_counter, 1);
        __syncthreads();
        const int n = s_batch;
        if (n >= BB) break;                    // uniform exit
        const int b = g_order[n];

        const float* potb = pot + (size_t)b * TT * CC;
        int L = seq_len[b];
        if (L > TT) L = TT;
        if (L < 1)  L = 1;

        if (h == 0) s_score[0][j] = potb[j];
        __syncthreads();

        int buf = 0;
        for (int t = 1; t < L; ++t) {
            float pv = potb[t * CC + j];

            // this thread's 24 scores (96-byte-aligned float4 loads)
            float sc[HALF];
            const float4* s4 = reinterpret_cast<const float4*>(&s_score[buf][h * HALF]);
#pragma unroll
            for (int q = 0; q < HALF / 4; ++q) {
                float4 v4 = s4[q];
                sc[4 * q + 0] = v4.x; sc[4 * q + 1] = v4.y;
                sc[4 * q + 2] = v4.z; sc[4 * q + 3] = v4.w;
            }

            // sums via packed f32x2 adds
            float v[HALF];
#pragma unroll
            for (int q = 0; q < HALF / 2; ++q)
                addf32x2(v[2 * q], v[2 * q + 1],
                         sc[2 * q], sc[2 * q + 1],
                         c[2 * q],  c[2 * q + 1]);

            // local argmax tree 24->12->6->3->1; strict '>' on the
            // higher-index side => first-max-wins
            float val[12]; int id[12];
#pragma unroll
            for (int q = 0; q < 12; ++q) {
                bool p = v[2 * q + 1] > v[2 * q];
                val[q] = p ? v[2 * q + 1] : v[2 * q];
                id[q]  = p ? (2 * q + 1) : (2 * q);
            }
#pragma unroll
            for (int q = 0; q < 6; ++q) {
                bool p = val[2 * q + 1] > val[2 * q];
                val[q] = p ? val[2 * q + 1] : val[2 * q];
                id[q]  = p ? id[2 * q + 1]  : id[2 * q];
            }
#pragma unroll
            for (int q = 0; q < 3; ++q) {
                bool p = val[2 * q + 1] > val[2 * q];
                val[q] = p ? val[2 * q + 1] : val[2 * q];
                id[q]  = p ? id[2 * q + 1]  : id[2 * q];
            }
            bool  p1 = val[1] > val[0];
            float mv = p1 ? val[1] : val[0];
            int   ma = p1 ? id[1]  : id[0];
            bool  p2 = val[2] > mv;
            mv = p2 ? val[2] : mv;
            ma = p2 ? id[2]  : ma;
            ma += h * HALF;                 // globalize index

            // combine the two halves (pair lanes 2j,2j+1: same warp)
            float ov = __shfl_xor_sync(0xFFFFFFFFu, mv, 1);
            int   oa = __shfl_xor_sync(0xFFFFFFFFu, ma, 1);

            float lo_v = h ? ov : mv;  int lo_a = h ? oa : ma;
            float hi_v = h ? mv : ov;  int hi_a = h ? ma : oa;
            bool  p  = hi_v > lo_v;
            float bv = p ? hi_v : lo_v;
            int   bi = p ? hi_a : lo_a;

            if (h) s_score[buf ^ 1][j]    = bv + pv;
            else   s_bp[(t - 1) * CC + j] = (unsigned char)bi;
            buf ^= 1;
            __syncthreads();   // ping-pong: one barrier per step
        }

        // final argmax over last score (first-max wins)
        if (tid == 0) {
            float bestv = s_score[buf][0];
            int tag = 0;
#pragma unroll
            for (int i = 1; i < CC; ++i) {
                float v = s_score[buf][i];
                if (v > bestv) { bestv = v; tag = i; }
            }
            s_lasttag = tag;
        }
        __syncthreads();

        const int tag0 = s_lasttag;
        // parallel fill of the identity tail
        for (int t = L - 1 + tid; t < TT; t += NTH) s_tags[t] = (unsigned char)tag0;

        // serial backtrack (shared-mem pointer chase)
        if (tid == 0) {
            int tag = tag0;
            for (int t = L - 1; t >= 1; --t) {
                tag = s_bp[(t - 1) * CC + tag];
                s_tags[t - 1] = (unsigned char)tag;
            }
        }
        __syncthreads();

        // one-hot output: float4 stores, coalesced
        float4* ob = reinterpret_cast<float4*>(out + (size_t)b * TT * CC);
        const int NQ = TT * (CC / 4);   // 6144 quads per batch row
        for (int q = tid; q < NQ; q += NTH) {
            int t   = q / (CC / 4);
            int r   = q % (CC / 4);
            int tag = s_tags[t];
            int e   = r * 4;
            float4 v;
            v.x = (e + 0 == tag) ? 1.0f : 0.0f;
            v.y = (e + 1 == tag) ? 1.0f : 0.0f;
            v.z = (e + 2 == tag) ? 1.0f : 0.0f;
            v.w = (e + 3 == tag) ? 1.0f : 0.0f;
            ob[q] = v;
        }
    }
}

extern "C" void kernel_launch(void* const* d_in, const int* in_sizes, int n_in,
                              void* d_out, int out_size)
{
    const float* pot    = (const float*)d_in[0];
    const int*   seqlen = (const int*)d_in[1];
    const float* trans  = (const float*)d_in[2];
    float*       out    = (float*)d_out;

    order_kernel<<<1, TT>>>(seqlen);
    viterbi_kernel<<<NBLK, NTH>>>(pot, seqlen, trans, out);
}